// round 9
// baseline (speedup 1.0000x reference)
#include <cuda_runtime.h>
#include <cuda_fp16.h>
#include <cstdint>
#include <cstddef>

// Problem dims (fixed)
#define BB 4
#define KSEQ 4096
#define DD 2048
#define M_TOTAL (BB * KSEQ)   // 16384

// Device scratch (__device__ globals per allocation rules)
__device__ float  g_lam[(size_t)M_TOTAL * DD];   // 128 MB
__device__ __half g_xh [(size_t)M_TOTAL * DD];   // 64 MB
__device__ __half g_wh [(size_t)DD * DD];        // 8 MB

// ---------------------------------------------------------------------------
// GEMM + bias + sigmoid via mma.sync m16n8k16 fp16 (f32 accumulate):
//   g_lam[m,e] = sigmoid( sum_d x[m,d] * W[e,d] + b[e] )
// Block 128x128x64(halves), 256 threads (8 warps 2x4), warp tile 64x32.
// 3-stage cp.async pipeline. Smem rows = 64 halves padded to 72 (144B):
// fragment LDS bank = (4*row + t4 [+4]) mod 32 -> all 32 lanes distinct.
// __launch_bounds__(256, 1): 255-reg ceiling -- NO spills (R7/R8 failure was
// the 128-reg cap from min-blocks=2 spilling the 64 accumulator regs).
// ---------------------------------------------------------------------------
#define Bb 128            // block M
#define BN 128            // block N
#define BKH 64            // block K in halves
#define STAGES 3
#define PADH 72           // halves per smem row (144 B)
#define A_ST_HALVES (Bb * PADH)
#define B_ST_HALVES (BN * PADH)
#define STAGE_HALVES (A_ST_HALVES + B_ST_HALVES)
#define GEMM_SMEM (STAGES * STAGE_HALVES * 2)     // 110592 B
#define GEMM_THREADS 256

__device__ __forceinline__ uint32_t smem_u32(const void* p) {
    uint32_t a;
    asm("{ .reg .u64 t; cvta.to.shared.u64 t, %1; cvt.u32.u64 %0, t; }" : "=r"(a) : "l"(p));
    return a;
}
__device__ __forceinline__ void cpa16(uint32_t dst, const void* src) {
    asm volatile("cp.async.cg.shared.global [%0], [%1], 16;" :: "r"(dst), "l"(src) : "memory");
}
#define CP_COMMIT() asm volatile("cp.async.commit_group;" ::: "memory")
#define CP_WAIT(n)  asm volatile("cp.async.wait_group %0;" :: "n"(n) : "memory")

__device__ __forceinline__ float sigmoidf_fast(float z) {
    return 1.0f / (1.0f + __expf(-z));
}
__device__ __forceinline__ uint32_t lds32(uint32_t addr) {
    uint32_t v;
    asm volatile("ld.shared.b32 %0, [%1];" : "=r"(v) : "r"(addr));
    return v;
}

// ---------------- convert fp32 -> fp16 --------------------------------------
__global__ void tohalf_kernel(const float* __restrict__ src,
                              __half* __restrict__ dst, int n4) {
    int i = blockIdx.x * blockDim.x + threadIdx.x;
    int stride = gridDim.x * blockDim.x;
    __half2* d2 = (__half2*)dst;
    for (; i < n4; i += stride) {
        float4 v = ((const float4*)src)[i];
        d2[2 * i]     = __floats2half2_rn(v.x, v.y);
        d2[2 * i + 1] = __floats2half2_rn(v.z, v.w);
    }
}

// ---------------- GEMM kernel ------------------------------------------------
__global__ __launch_bounds__(GEMM_THREADS, 1)
void gemm_sigmoid_kernel(const __half* __restrict__ A,     // x fp16 [M, D]
                         const __half* __restrict__ W,     // W fp16 [E, D]
                         const float* __restrict__ bias) {
    extern __shared__ __half smem[];
    const int tid  = threadIdx.x;
    const int warp = tid >> 5;
    const int lane = tid & 31;
    const int m0   = blockIdx.y * Bb;
    const int n0   = blockIdx.x * BN;
    const int wm   = (warp >> 2) * 64;     // warp rows (2)
    const int wn   = (warp & 3) * 32;      // warp cols (4)
    const int g    = lane >> 2;            // 0..7
    const int t4   = lane & 3;             // 0..3

    const int ldr = tid >> 3;              // cp.async row 0..31
    const int lds = tid & 7;               // 16B segment 0..7

    const uint32_t smem_base = smem_u32(smem);
    // per-thread fragment byte offsets within a stage (32-bit smem math only)
    const uint32_t aFragOff = (uint32_t)((wm + g) * PADH + 2 * t4) * 2u;
    const uint32_t bFragOff = (uint32_t)(A_ST_HALVES + (wn + g) * PADH + 2 * t4) * 2u;

    float acc[4][4][4];
#pragma unroll
    for (int i = 0; i < 4; i++)
#pragma unroll
        for (int j = 0; j < 4; j++)
#pragma unroll
            for (int c = 0; c < 4; c++) acc[i][j][c] = 0.0f;

    const int NKT = DD / BKH;   // 32 chunks

    auto load_stage = [&](int kt, int s) {
        const int kk = kt * BKH;
        const uint32_t sa = smem_base + (uint32_t)(s * STAGE_HALVES) * 2u;
        const uint32_t sb = sa + (uint32_t)A_ST_HALVES * 2u;
#pragma unroll
        for (int i = 0; i < 4; i++) {
            int row = i * 32 + ldr;        // 0..127
            cpa16(sa + (uint32_t)(row * PADH + lds * 8) * 2u,
                  A + (size_t)(m0 + row) * DD + kk + lds * 8);
        }
#pragma unroll
        for (int i = 0; i < 4; i++) {
            int row = i * 32 + ldr;
            cpa16(sb + (uint32_t)(row * PADH + lds * 8) * 2u,
                  W + (size_t)(n0 + row) * DD + kk + lds * 8);
        }
        CP_COMMIT();
    };

    load_stage(0, 0);
    load_stage(1, 1);

    for (int kt = 0; kt < NKT; kt++) {
        CP_WAIT(STAGES - 2);
        __syncthreads();

        const int s = kt % STAGES;
        const uint32_t stageB = smem_base + (uint32_t)(s * STAGE_HALVES) * 2u;
        const uint32_t aB = stageB + aFragOff;
        const uint32_t bB = stageB + bFragOff;

#pragma unroll
        for (int ks = 0; ks < BKH / 16; ks++) {          // 4 k16 steps
            const uint32_t kOff = (uint32_t)(ks * 16) * 2u;
            // A fragments: 4 regs each (row g / g+8, k-lo pair / k-hi pair)
            uint32_t afr[4][4];
#pragma unroll
            for (int mt = 0; mt < 4; mt++) {
                const uint32_t ap = aB + (uint32_t)(mt * 16 * PADH) * 2u + kOff;
                afr[mt][0] = lds32(ap);
                afr[mt][1] = lds32(ap + 8 * PADH * 2);
                afr[mt][2] = lds32(ap + 16);
                afr[mt][3] = lds32(ap + 8 * PADH * 2 + 16);
            }
            // B fragments: 2 regs each (k-pairs 2t4 / 2t4+8, col g)
            uint32_t bfr[4][2];
#pragma unroll
            for (int nt = 0; nt < 4; nt++) {
                const uint32_t bp = bB + (uint32_t)(nt * 8 * PADH) * 2u + kOff;
                bfr[nt][0] = lds32(bp);
                bfr[nt][1] = lds32(bp + 16);
            }
#pragma unroll
            for (int mt = 0; mt < 4; mt++) {
#pragma unroll
                for (int nt = 0; nt < 4; nt++) {
                    asm volatile(
                        "mma.sync.aligned.m16n8k16.row.col.f32.f16.f16.f32 "
                        "{%0,%1,%2,%3}, {%4,%5,%6,%7}, {%8,%9}, {%0,%1,%2,%3};"
                        : "+f"(acc[mt][nt][0]), "+f"(acc[mt][nt][1]),
                          "+f"(acc[mt][nt][2]), "+f"(acc[mt][nt][3])
                        : "r"(afr[mt][0]), "r"(afr[mt][1]),
                          "r"(afr[mt][2]), "r"(afr[mt][3]),
                          "r"(bfr[nt][0]), "r"(bfr[nt][1]));
                }
            }
        }
        __syncthreads();

        if (kt + STAGES - 1 < NKT)
            load_stage(kt + STAGES - 1, (kt + STAGES - 1) % STAGES);
        else
            CP_COMMIT();   // keep group count consistent
    }

    // Epilogue: bias + sigmoid -> g_lam (float2 per nt)
#pragma unroll
    for (int mt = 0; mt < 4; mt++) {
#pragma unroll
        for (int half = 0; half < 2; half++) {
            const int row = m0 + wm + mt * 16 + g + half * 8;
            float* dst = g_lam + (size_t)row * DD;
#pragma unroll
            for (int nt = 0; nt < 4; nt++) {
                const int col = n0 + wn + nt * 8 + t4 * 2;
                float2 v;
                v.x = sigmoidf_fast(acc[mt][nt][2 * half + 0] + __ldg(bias + col));
                v.y = sigmoidf_fast(acc[mt][nt][2 * half + 1] + __ldg(bias + col + 1));
                *reinterpret_cast<float2*>(dst + col) = v;
            }
        }
    }
}

// ---------------- chunked 2-phase scan (at DRAM roofline) -------------------
#define SC_CHUNKS 32
#define SC_L (KSEQ / SC_CHUNKS)   // 128
__global__ __launch_bounds__(1024)
void scan_kernel(const float* __restrict__ x, float* __restrict__ out) {
    __shared__ float sP[SC_CHUNKS][33];
    __shared__ float sQ[SC_CHUNKS][33];
    const int lane = threadIdx.x & 31;
    const int ck   = threadIdx.x >> 5;
    const int ch   = blockIdx.x * 32 + lane;
    const int b    = ch >> 11;
    const int d    = ch & (DD - 1);
    const size_t base = ((size_t)b * KSEQ + (size_t)ck * SC_L) * DD + d;

    float s = 0.0f, p = 1.0f;
    {
        size_t idx = base;
#pragma unroll 4
        for (int j = 0; j < SC_L; j++) {
            float lm = __ldg(g_lam + idx);
            float u  = __ldg(x + idx);
            s = fmaf(lm, s - u, u);
            p *= lm;
            idx += DD;
        }
    }
    sP[ck][lane] = p;
    sQ[ck][lane] = s;
    __syncthreads();

    float carry = 0.0f;
    for (int j = 0; j < ck; j++) carry = fmaf(sP[j][lane], carry, sQ[j][lane]);

    {
        size_t idx = base;
        float ss = carry;
#pragma unroll 4
        for (int j = 0; j < SC_L; j++) {
            float lm = __ldg(g_lam + idx);
            float u  = __ldg(x + idx);
            ss = fmaf(lm, ss - u, u);
            out[idx] = ss;
            idx += DD;
        }
    }
}

// ---------------------------------------------------------------------------
extern "C" void kernel_launch(void* const* d_in, const int* in_sizes, int n_in,
                              void* d_out, int out_size) {
    const float* x    = (const float*)d_in[0];   // [B,K,D]
    const float* W    = (const float*)d_in[1];   // [D,D]
    const float* bias = (const float*)d_in[2];   // [D]
    float* out = (float*)d_out;                  // [B,K,D]

    cudaFuncSetAttribute(gemm_sigmoid_kernel,
                         cudaFuncAttributeMaxDynamicSharedMemorySize, GEMM_SMEM);

    tohalf_kernel<<<4096, 256>>>(x, g_xh, (M_TOTAL * DD) / 4);
    tohalf_kernel<<<1024, 256>>>(W, g_wh, (DD * DD) / 4);

    dim3 ggrid(DD / BN, M_TOTAL / Bb);           // (16, 128)
    gemm_sigmoid_kernel<<<ggrid, GEMM_THREADS, GEMM_SMEM>>>(g_xh, g_wh, bias);

    scan_kernel<<<(BB * DD) / 32, 1024>>>(x, out);
}

// round 10
// speedup vs baseline: 6.1898x; 6.1898x over previous
#include <cuda_runtime.h>
#include <cstdint>
#include <cstddef>

// Problem dims (fixed)
#define BB 4
#define KSEQ 4096
#define DD 2048
#define M_TOTAL (BB * KSEQ)   // 16384

// Scratch: lam[m,e] fp32 (128 MB). __device__ global per allocation rules.
__device__ float g_lam[(size_t)M_TOTAL * DD];

// ---------------------------------------------------------------------------
// GEMM + bias + sigmoid via tf32 mma.sync m16n8k8 (THE proven-fast tensor path
// on this sm_103 toolchain; fp16/ldmatrix variants measured 17-34x slower).
// Block 256x256x32, 512 threads (16 warps, 4x4), warp tile 64x64.
// 3-stage cp.async pipeline (221KB smem, 1 CTA/SM). Smem rows padded to 36
// floats: fragment LDS bank = (4*row + k) mod 32 -> all 32 lanes distinct.
// vs R5 (128x128): A/B gmem traffic 4GB -> 2GB.
// ---------------------------------------------------------------------------
#define Bb 256            // block M
#define BN 256            // block N
#define BK 32             // block K
#define STAGES 3
#define PAD 36            // floats per smem row
#define A_ST_FLOATS (Bb * PAD)
#define B_ST_FLOATS (BN * PAD)
#define STAGE_FLOATS (A_ST_FLOATS + B_ST_FLOATS)
#define GEMM_SMEM (STAGES * STAGE_FLOATS * 4)     // 221184 B
#define GEMM_THREADS 512

__device__ __forceinline__ uint32_t smem_u32(const void* p) {
    uint32_t a;
    asm("{ .reg .u64 t; cvta.to.shared.u64 t, %1; cvt.u32.u64 %0, t; }" : "=r"(a) : "l"(p));
    return a;
}
__device__ __forceinline__ void cpa16(uint32_t dst, const void* src) {
    asm volatile("cp.async.cg.shared.global [%0], [%1], 16;" :: "r"(dst), "l"(src) : "memory");
}
#define CP_COMMIT() asm volatile("cp.async.commit_group;" ::: "memory")
#define CP_WAIT(n)  asm volatile("cp.async.wait_group %0;" :: "n"(n) : "memory")

__device__ __forceinline__ uint32_t f32_to_tf32(float v) {
    uint32_t r;
    asm("cvt.rna.tf32.f32 %0, %1;" : "=r"(r) : "f"(v));
    return r;
}
__device__ __forceinline__ float sigmoidf_fast(float z) {
    return 1.0f / (1.0f + __expf(-z));
}

__global__ __launch_bounds__(GEMM_THREADS, 1)
void gemm_sigmoid_kernel(const float* __restrict__ A,      // x [M, D]
                         const float* __restrict__ W,      // W [E, D]
                         const float* __restrict__ bias) {
    extern __shared__ float smem[];
    const int tid  = threadIdx.x;
    const int warp = tid >> 5;
    const int lane = tid & 31;
    const int m0   = blockIdx.y * Bb;
    const int n0   = blockIdx.x * BN;
    const int wm   = (warp >> 2) * 64;     // 4 warp-rows of 64
    const int wn   = (warp & 3) * 64;      // 4 warp-cols of 64
    const int g    = lane >> 2;            // 0..7
    const int t4   = lane & 3;             // 0..3

    const int ldr = tid >> 3;              // cp.async row 0..63
    const int lds = tid & 7;               // 16B segment 0..7

    const uint32_t smem_base = smem_u32(smem);

    float acc[4][8][4];                    // 128 accumulators
#pragma unroll
    for (int i = 0; i < 4; i++)
#pragma unroll
        for (int j = 0; j < 8; j++)
#pragma unroll
            for (int c = 0; c < 4; c++) acc[i][j][c] = 0.0f;

    const int NKT = DD / BK;   // 64 chunks

    auto load_stage = [&](int kt, int s) {
        const int kk = kt * BK;
        const uint32_t sa = smem_base + (uint32_t)(s * STAGE_FLOATS) * 4u;
        const uint32_t sb = sa + (uint32_t)A_ST_FLOATS * 4u;
#pragma unroll
        for (int i = 0; i < 4; i++) {
            int row = i * 64 + ldr;        // 0..255
            cpa16(sa + (uint32_t)(row * PAD + lds * 4) * 4u,
                  A + (size_t)(m0 + row) * DD + kk + lds * 4);
        }
#pragma unroll
        for (int i = 0; i < 4; i++) {
            int row = i * 64 + ldr;
            cpa16(sb + (uint32_t)(row * PAD + lds * 4) * 4u,
                  W + (size_t)(n0 + row) * DD + kk + lds * 4);
        }
        CP_COMMIT();
    };

    load_stage(0, 0);
    load_stage(1, 1);

    for (int kt = 0; kt < NKT; kt++) {
        CP_WAIT(STAGES - 2);
        __syncthreads();

        const int s = kt % STAGES;
        const float* sA = smem + s * STAGE_FLOATS;
        const float* sB = sA + A_ST_FLOATS;

#pragma unroll
        for (int ks = 0; ks < BK; ks += 8) {
            // A fragments: 4 m-tiles (64 rows)
            uint32_t afr[4][4];
#pragma unroll
            for (int mt = 0; mt < 4; mt++) {
                const float* ap = sA + (wm + mt * 16 + g) * PAD + ks + t4;
                afr[mt][0] = f32_to_tf32(ap[0]);
                afr[mt][1] = f32_to_tf32(ap[8 * PAD]);
                afr[mt][2] = f32_to_tf32(ap[4]);
                afr[mt][3] = f32_to_tf32(ap[8 * PAD + 4]);
            }
            // B fragments: 8 n-tiles (64 cols)
            uint32_t bfr[8][2];
#pragma unroll
            for (int nt = 0; nt < 8; nt++) {
                const float* bp = sB + (wn + nt * 8 + g) * PAD + ks + t4;
                bfr[nt][0] = f32_to_tf32(bp[0]);
                bfr[nt][1] = f32_to_tf32(bp[4]);
            }
#pragma unroll
            for (int mt = 0; mt < 4; mt++) {
#pragma unroll
                for (int nt = 0; nt < 8; nt++) {
                    asm volatile(
                        "mma.sync.aligned.m16n8k8.row.col.f32.tf32.tf32.f32 "
                        "{%0,%1,%2,%3}, {%4,%5,%6,%7}, {%8,%9}, {%0,%1,%2,%3};"
                        : "+f"(acc[mt][nt][0]), "+f"(acc[mt][nt][1]),
                          "+f"(acc[mt][nt][2]), "+f"(acc[mt][nt][3])
                        : "r"(afr[mt][0]), "r"(afr[mt][1]),
                          "r"(afr[mt][2]), "r"(afr[mt][3]),
                          "r"(bfr[nt][0]), "r"(bfr[nt][1]));
                }
            }
        }
        __syncthreads();

        if (kt + STAGES - 1 < NKT)
            load_stage(kt + STAGES - 1, (kt + STAGES - 1) % STAGES);
        else
            CP_COMMIT();   // keep group count consistent
    }

    // Epilogue: bias + sigmoid -> g_lam (float2 stores)
#pragma unroll
    for (int mt = 0; mt < 4; mt++) {
#pragma unroll
        for (int half = 0; half < 2; half++) {
            const int row = m0 + wm + mt * 16 + g + half * 8;
            float* dst = g_lam + (size_t)row * DD;
#pragma unroll
            for (int nt = 0; nt < 8; nt++) {
                const int col = n0 + wn + nt * 8 + t4 * 2;
                float2 v;
                v.x = sigmoidf_fast(acc[mt][nt][2 * half + 0] + __ldg(bias + col));
                v.y = sigmoidf_fast(acc[mt][nt][2 * half + 1] + __ldg(bias + col + 1));
                *reinterpret_cast<float2*>(dst + col) = v;
            }
        }
    }
}

// ---------------- chunked 2-phase scan (at DRAM roofline) -------------------
#define SC_CHUNKS 32
#define SC_L (KSEQ / SC_CHUNKS)   // 128
__global__ __launch_bounds__(1024)
void scan_kernel(const float* __restrict__ x, float* __restrict__ out) {
    __shared__ float sP[SC_CHUNKS][33];
    __shared__ float sQ[SC_CHUNKS][33];
    const int lane = threadIdx.x & 31;
    const int ck   = threadIdx.x >> 5;
    const int ch   = blockIdx.x * 32 + lane;
    const int b    = ch >> 11;
    const int d    = ch & (DD - 1);
    const size_t base = ((size_t)b * KSEQ + (size_t)ck * SC_L) * DD + d;

    float s = 0.0f, p = 1.0f;
    {
        size_t idx = base;
#pragma unroll 4
        for (int j = 0; j < SC_L; j++) {
            float lm = __ldg(g_lam + idx);
            float u  = __ldg(x + idx);
            s = fmaf(lm, s - u, u);
            p *= lm;
            idx += DD;
        }
    }
    sP[ck][lane] = p;
    sQ[ck][lane] = s;
    __syncthreads();

    float carry = 0.0f;
    for (int j = 0; j < ck; j++) carry = fmaf(sP[j][lane], carry, sQ[j][lane]);

    {
        size_t idx = base;
        float ss = carry;
#pragma unroll 4
        for (int j = 0; j < SC_L; j++) {
            float lm = __ldg(g_lam + idx);
            float u  = __ldg(x + idx);
            ss = fmaf(lm, ss - u, u);
            out[idx] = ss;
            idx += DD;
        }
    }
}

// ---------------------------------------------------------------------------
extern "C" void kernel_launch(void* const* d_in, const int* in_sizes, int n_in,
                              void* d_out, int out_size) {
    const float* x    = (const float*)d_in[0];   // [B,K,D]
    const float* W    = (const float*)d_in[1];   // [D,D]
    const float* bias = (const float*)d_in[2];   // [D]
    float* out = (float*)d_out;                  // [B,K,D]

    cudaFuncSetAttribute(gemm_sigmoid_kernel,
                         cudaFuncAttributeMaxDynamicSharedMemorySize, GEMM_SMEM);

    dim3 ggrid(DD / BN, M_TOTAL / Bb);           // (8, 64)
    gemm_sigmoid_kernel<<<ggrid, GEMM_THREADS, GEMM_SMEM>>>(x, W, bias);

    scan_kernel<<<(BB * DD) / 32, 1024>>>(x, out);
}